// round 1
// baseline (speedup 1.0000x reference)
#include <cuda_runtime.h>
#include <cstddef>

#define TOTAL   8192
#define DIM     1280
#define HEADS   16
#define HD      80
#define NCHUNKS 8
#define CHUNK   1024
#define K_DIM   1280

// Scratch (device globals — no allocation allowed in kernel_launch)
__device__ float g_q [TOTAL * DIM];
__device__ float g_k [TOTAL * DIM];
__device__ float g_v [TOTAL * DIM];
__device__ float g_ao[TOTAL * DIM];

// ---------------------------------------------------------------------------
// SGEMM: C[M,N] = A[M,K] @ W[N,K]^T + bias[N]
// BM=128, BN=128, BK=16, 256 threads, 8x8 register tile per thread.
// EPI==0: scatter QKV output into g_q/g_k/g_v (col -> part*1280 + cc)
// EPI==1: plain store to O0 (N == DIM)
// ---------------------------------------------------------------------------
template <int EPI>
__global__ __launch_bounds__(256)
void sgemm_kernel(const float* __restrict__ A, const float* __restrict__ W,
                  const float* __restrict__ bias,
                  float* __restrict__ O0, float* __restrict__ O1,
                  float* __restrict__ O2)
{
    __shared__ float As[16][132];
    __shared__ float Bs[16][132];

    const int tid = threadIdx.x;
    const int tx  = tid & 15;      // 0..15  (n direction)
    const int ty  = tid >> 4;      // 0..15  (m direction)
    const int m0  = blockIdx.y * 128;
    const int n0  = blockIdx.x * 128;

    float acc[8][8];
#pragma unroll
    for (int i = 0; i < 8; i++)
#pragma unroll
        for (int j = 0; j < 8; j++) acc[i][j] = 0.f;

    for (int kt = 0; kt < K_DIM; kt += 16) {
        // Load 128x16 tiles of A and W (as B^T) into smem, transposed to [k][m]/[k][n]
#pragma unroll
        for (int t = 0; t < 2; t++) {
            int idx = tid + t * 256;           // 0..511
            int r   = idx >> 2;                // 0..127
            int c4  = (idx & 3) * 4;           // 0,4,8,12
            float4 fa = *(const float4*)&A[(size_t)(m0 + r) * K_DIM + kt + c4];
            As[c4 + 0][r] = fa.x; As[c4 + 1][r] = fa.y;
            As[c4 + 2][r] = fa.z; As[c4 + 3][r] = fa.w;
            float4 fb = *(const float4*)&W[(size_t)(n0 + r) * K_DIM + kt + c4];
            Bs[c4 + 0][r] = fb.x; Bs[c4 + 1][r] = fb.y;
            Bs[c4 + 2][r] = fb.z; Bs[c4 + 3][r] = fb.w;
        }
        __syncthreads();

#pragma unroll
        for (int kk = 0; kk < 16; kk++) {
            float ra[8], rb[8];
            *(float4*)&ra[0] = *(float4*)&As[kk][ty * 8];
            *(float4*)&ra[4] = *(float4*)&As[kk][ty * 8 + 4];
            *(float4*)&rb[0] = *(float4*)&Bs[kk][tx * 8];
            *(float4*)&rb[4] = *(float4*)&Bs[kk][tx * 8 + 4];
#pragma unroll
            for (int i = 0; i < 8; i++)
#pragma unroll
                for (int j = 0; j < 8; j++)
                    acc[i][j] += ra[i] * rb[j];
        }
        __syncthreads();
    }

    // Epilogue
#pragma unroll
    for (int i = 0; i < 8; i++) {
        int row = m0 + ty * 8 + i;
#pragma unroll
        for (int j = 0; j < 8; j++) {
            int   col = n0 + tx * 8 + j;
            float v   = acc[i][j] + bias[col];
            if (EPI == 0) {
                int part = col / DIM;
                int cc   = col - part * DIM;
                float* dst = (part == 0) ? O0 : (part == 1 ? O1 : O2);
                dst[(size_t)row * DIM + cc] = v;
            } else {
                O0[(size_t)row * DIM + col] = v;
            }
        }
    }
}

// ---------------------------------------------------------------------------
// RoPE: q' = q*cos + rotate_half(q)*sin  (in place on g_q and g_k)
// One block per token; each thread handles (d, d+40) pairs.
// ---------------------------------------------------------------------------
__global__ void rope_kernel(float* __restrict__ q, float* __restrict__ k,
                            const float* __restrict__ cosb,
                            const float* __restrict__ sinb)
{
    int t = blockIdx.x;
    for (int p = threadIdx.x; p < HEADS * 40; p += blockDim.x) {
        int h = p / 40, d = p - (p / 40) * 40;
        size_t base = (size_t)t * DIM + h * HD;
        float c0 = cosb[t * HD + d],      s0 = sinb[t * HD + d];
        float c1 = cosb[t * HD + d + 40], s1 = sinb[t * HD + d + 40];

        float a = q[base + d], b = q[base + d + 40];
        q[base + d]      = a * c0 - b * s0;
        q[base + d + 40] = b * c1 + a * s1;

        a = k[base + d]; b = k[base + d + 40];
        k[base + d]      = a * c0 - b * s0;
        k[base + d + 40] = b * c1 + a * s1;
    }
}

// ---------------------------------------------------------------------------
// Flash attention, fp32. Block = (qtile of 128, head, chunk), 128 threads.
// Each thread owns one query row: q[80] and o[80] in registers.
// Keys/values staged in smem in tiles of 64 rows (padded to 84 for banks).
// ---------------------------------------------------------------------------
__global__ __launch_bounds__(128)
void attn_kernel(const float* __restrict__ qb, const float* __restrict__ kb,
                 const float* __restrict__ vb, float* __restrict__ ob)
{
    __shared__ float Ks[64][84];
    __shared__ float Vs[64][84];

    const int chunk = blockIdx.z;
    const int head  = blockIdx.y;
    const int qt    = blockIdx.x;
    const int tid   = threadIdx.x;
    const int qrow  = chunk * CHUNK + qt * 128 + tid;

    const float scale = 0.11180339887498948f;  // 80^-0.5

    float q[HD];
    const float* qp = qb + (size_t)qrow * DIM + head * HD;
#pragma unroll
    for (int d = 0; d < HD; d += 4) {
        float4 f = *(const float4*)&qp[d];
        q[d] = f.x * scale; q[d + 1] = f.y * scale;
        q[d + 2] = f.z * scale; q[d + 3] = f.w * scale;
    }

    float o[HD];
#pragma unroll
    for (int d = 0; d < HD; d++) o[d] = 0.f;
    float m = -1e30f, l = 0.f;

    for (int kt0 = 0; kt0 < CHUNK; kt0 += 64) {
        __syncthreads();
        const float* kp = kb + (size_t)(chunk * CHUNK + kt0) * DIM + head * HD;
        const float* vp = vb + (size_t)(chunk * CHUNK + kt0) * DIM + head * HD;
        // 64 rows * 20 float4 = 1280 float4 loads, coalesced in runs of 20
        for (int i = tid; i < 64 * 20; i += 128) {
            int r = i / 20;
            int c = (i - r * 20) * 4;
            *(float4*)&Ks[r][c] = *(const float4*)&kp[(size_t)r * DIM + c];
            *(float4*)&Vs[r][c] = *(const float4*)&vp[(size_t)r * DIM + c];
        }
        __syncthreads();

#pragma unroll 2
        for (int j = 0; j < 64; j++) {
            float s = 0.f;
#pragma unroll
            for (int d = 0; d < HD; d += 4) {
                float4 kk = *(float4*)&Ks[j][d];
                s += q[d] * kk.x + q[d + 1] * kk.y
                   + q[d + 2] * kk.z + q[d + 3] * kk.w;
            }
            if (s > m) {                        // rare after warmup
                float alpha = __expf(m - s);
                m = s;
                l *= alpha;
#pragma unroll
                for (int d = 0; d < HD; d++) o[d] *= alpha;
            }
            float p = __expf(s - m);
            l += p;
#pragma unroll
            for (int d = 0; d < HD; d += 4) {
                float4 vv = *(float4*)&Vs[j][d];
                o[d]     += p * vv.x; o[d + 1] += p * vv.y;
                o[d + 2] += p * vv.z; o[d + 3] += p * vv.w;
            }
        }
    }

    float inv = 1.f / l;
    float* op = ob + (size_t)qrow * DIM + head * HD;
#pragma unroll
    for (int d = 0; d < HD; d += 4) {
        float4 f;
        f.x = o[d] * inv;     f.y = o[d + 1] * inv;
        f.z = o[d + 2] * inv; f.w = o[d + 3] * inv;
        *(float4*)&op[d] = f;
    }
}

// ---------------------------------------------------------------------------
// Launch: QKV GEMM -> RoPE -> attention -> proj GEMM
// Inputs: hidden_states, cos, sin, qkv_w, qkv_b, proj_w, proj_b, cu_seqlens
// ---------------------------------------------------------------------------
extern "C" void kernel_launch(void* const* d_in, const int* in_sizes, int n_in,
                              void* d_out, int out_size)
{
    const float* hs    = (const float*)d_in[0];
    const float* cosb  = (const float*)d_in[1];
    const float* sinb  = (const float*)d_in[2];
    const float* qkvw  = (const float*)d_in[3];
    const float* qkvb  = (const float*)d_in[4];
    const float* projw = (const float*)d_in[5];
    const float* projb = (const float*)d_in[6];
    float* out = (float*)d_out;
    (void)in_sizes; (void)n_in; (void)out_size;

    float *gq, *gk, *gv, *gao;
    cudaGetSymbolAddress((void**)&gq,  g_q);
    cudaGetSymbolAddress((void**)&gk,  g_k);
    cudaGetSymbolAddress((void**)&gv,  g_v);
    cudaGetSymbolAddress((void**)&gao, g_ao);

    // QKV projection: (8192,1280) @ (3840,1280)^T + bias, scattered to q/k/v
    sgemm_kernel<0><<<dim3(3 * DIM / 128, TOTAL / 128), 256>>>(
        hs, qkvw, qkvb, gq, gk, gv);

    // RoPE on q and k
    rope_kernel<<<TOTAL, 640>>>(gq, gk, cosb, sinb);

    // Attention per (chunk, head)
    attn_kernel<<<dim3(CHUNK / 128, HEADS, NCHUNKS), 128>>>(gq, gk, gv, gao);

    // Output projection: (8192,1280) @ (1280,1280)^T + bias
    sgemm_kernel<1><<<dim3(DIM / 128, TOTAL / 128), 256>>>(
        gao, projw, projb, out, nullptr, nullptr);
}

// round 3
// speedup vs baseline: 1.6618x; 1.6618x over previous
#include <cuda_runtime.h>
#include <cuda_bf16.h>
#include <cstdint>
#include <cstddef>

#define TOTAL   8192
#define DIM     1280
#define HEADS   16
#define HD      80
#define NCHUNKS 8
#define CHUNK   1024
#define K_DIM   1280
#define N_QKV   3840

// ---------------- scratch (device globals; no allocation allowed) ----------
__device__ float g_q [TOTAL * DIM];
__device__ float g_k [TOTAL * DIM];
__device__ float g_v [TOTAL * DIM];
__device__ float g_ao[TOTAL * DIM];

__device__ __nv_bfloat16 g_hs_hi[TOTAL * K_DIM];
__device__ __nv_bfloat16 g_hs_lo[TOTAL * K_DIM];
__device__ __nv_bfloat16 g_ao_hi[TOTAL * K_DIM];
__device__ __nv_bfloat16 g_ao_lo[TOTAL * K_DIM];
__device__ __nv_bfloat16 g_wq_hi[N_QKV * K_DIM];
__device__ __nv_bfloat16 g_wq_lo[N_QKV * K_DIM];
__device__ __nv_bfloat16 g_wp_hi[DIM * K_DIM];
__device__ __nv_bfloat16 g_wp_lo[DIM * K_DIM];

// ---------------- PTX helpers (baseline sm_80+ instructions only) ----------
__device__ __forceinline__ uint32_t smem_u32(const void* p) {
    uint32_t r;
    asm("{ .reg .u64 t; cvta.to.shared.u64 t, %1; cvt.u32.u64 %0, t; }"
        : "=r"(r) : "l"(p));
    return r;
}

__device__ __forceinline__ void cp16(uint32_t dst, const void* src) {
    asm volatile("cp.async.cg.shared.global [%0], [%1], 16;" :: "r"(dst), "l"(src));
}

__device__ __forceinline__ void ldmA(uint32_t* a, uint32_t addr) {
    asm volatile("ldmatrix.sync.aligned.m8n8.x4.shared.b16 {%0,%1,%2,%3}, [%4];"
                 : "=r"(a[0]), "=r"(a[1]), "=r"(a[2]), "=r"(a[3]) : "r"(addr));
}

__device__ __forceinline__ void ldmB(uint32_t* b, uint32_t addr) {
    asm volatile("ldmatrix.sync.aligned.m8n8.x2.shared.b16 {%0,%1}, [%2];"
                 : "=r"(b[0]), "=r"(b[1]) : "r"(addr));
}

__device__ __forceinline__ void mma16816(float* d, const uint32_t* a, const uint32_t* b) {
    asm volatile(
        "mma.sync.aligned.m16n8k16.row.col.f32.bf16.bf16.f32 "
        "{%0,%1,%2,%3}, {%4,%5,%6,%7}, {%8,%9}, {%0,%1,%2,%3};"
        : "+f"(d[0]), "+f"(d[1]), "+f"(d[2]), "+f"(d[3])
        : "r"(a[0]), "r"(a[1]), "r"(a[2]), "r"(a[3]), "r"(b[0]), "r"(b[1]));
}

// ---------------------------------------------------------------------------
// fp32 -> bf16 hi/lo split
// ---------------------------------------------------------------------------
__global__ void cvt_kernel(const float* __restrict__ x,
                           __nv_bfloat16* __restrict__ hi,
                           __nv_bfloat16* __restrict__ lo, int n4)
{
    int i = blockIdx.x * blockDim.x + threadIdx.x;
    if (i >= n4) return;
    float4 f = ((const float4*)x)[i];
    __nv_bfloat16 h0 = __float2bfloat16(f.x);
    __nv_bfloat16 h1 = __float2bfloat16(f.y);
    __nv_bfloat16 h2 = __float2bfloat16(f.z);
    __nv_bfloat16 h3 = __float2bfloat16(f.w);
    __nv_bfloat16 l0 = __float2bfloat16(f.x - __bfloat162float(h0));
    __nv_bfloat16 l1 = __float2bfloat16(f.y - __bfloat162float(h1));
    __nv_bfloat16 l2 = __float2bfloat16(f.z - __bfloat162float(h2));
    __nv_bfloat16 l3 = __float2bfloat16(f.w - __bfloat162float(h3));
    ((__nv_bfloat162*)hi)[i * 2 + 0] = __nv_bfloat162(h0, h1);
    ((__nv_bfloat162*)hi)[i * 2 + 1] = __nv_bfloat162(h2, h3);
    ((__nv_bfloat162*)lo)[i * 2 + 0] = __nv_bfloat162(l0, l1);
    ((__nv_bfloat162*)lo)[i * 2 + 1] = __nv_bfloat162(l2, l3);
}

// ---------------------------------------------------------------------------
// mma.sync GEMM: C[M,N] = A[M,K] @ W[N,K]^T + bias  (bf16 hi/lo, fp32 acc)
// 128x128 tile / CTA, 8 warps (2x4), 64x32 per warp, K-chunks of 32,
// 2-stage cp.async pipeline. Smem rows padded to 40 elems (80B) so
// ldmatrix phases hit distinct banks.
// EPI==0: scatter QKV columns to O0/O1/O2; EPI==1: plain store.
// ---------------------------------------------------------------------------
#define KC      32
#define NCH     40                    // 1280/32
#define STRIDE  40                    // elems per smem row (80B)
#define TILE_B  (128 * STRIDE * 2)    // 10240 B
#define STAGE_B (4 * TILE_B)          // 40960 B : Ah, Al, Bh, Bl

template <int EPI>
__global__ __launch_bounds__(256, 2)
void mma_gemm(const __nv_bfloat16* __restrict__ Ah, const __nv_bfloat16* __restrict__ Al,
              const __nv_bfloat16* __restrict__ Bh, const __nv_bfloat16* __restrict__ Bl,
              const float* __restrict__ bias,
              float* __restrict__ O0, float* __restrict__ O1, float* __restrict__ O2)
{
    extern __shared__ __nv_bfloat16 smem[];
    const uint32_t sbase = smem_u32(smem);

    const int tid  = threadIdx.x;
    const int wid  = tid >> 5;
    const int lane = tid & 31;
    const int m0   = blockIdx.y * 128;
    const int n0   = blockIdx.x * 128;
    const int wm   = (wid >> 2) * 64;   // warp M offset (0 or 64)
    const int wn   = (wid & 3) * 32;    // warp N offset

    const __nv_bfloat16* srcs[4] = {
        Ah + (size_t)m0 * K_DIM, Al + (size_t)m0 * K_DIM,
        Bh + (size_t)n0 * K_DIM, Bl + (size_t)n0 * K_DIM };

    auto load_chunk = [&](int stage, int ch) {
        const int k0 = ch * KC;
        const uint32_t sb = sbase + stage * STAGE_B;
#pragma unroll
        for (int t = 0; t < 8; t++) {
            int idx  = tid + t * 256;      // 0..2047
            int tile = idx >> 9;           // constant per t
            int rem  = idx & 511;
            int row  = rem >> 2;
            int seg  = rem & 3;
            cp16(sb + tile * TILE_B + row * (STRIDE * 2) + seg * 16,
                 srcs[tile] + (size_t)row * K_DIM + k0 + seg * 8);
        }
        asm volatile("cp.async.commit_group;");
    };

    float acc[4][4][4];
#pragma unroll
    for (int i = 0; i < 4; i++)
#pragma unroll
        for (int j = 0; j < 4; j++)
#pragma unroll
            for (int r = 0; r < 4; r++) acc[i][j][r] = 0.f;

    load_chunk(0, 0);

    for (int ch = 0; ch < NCH; ch++) {
        const int s = ch & 1;
        if (ch + 1 < NCH) {
            load_chunk(1 - s, ch + 1);
            asm volatile("cp.async.wait_group 1;");
        } else {
            asm volatile("cp.async.wait_group 0;");
        }
        __syncthreads();

        const uint32_t sb  = sbase + s * STAGE_B;
        const uint32_t sAh = sb;
        const uint32_t sAl = sb + TILE_B;
        const uint32_t sBh = sb + 2 * TILE_B;
        const uint32_t sBl = sb + 3 * TILE_B;

#pragma unroll
        for (int kk = 0; kk < KC; kk += 16) {
            uint32_t aH[16], aL[16];
            const int arow = lane & 15;
            const int acol = kk + (lane >> 4) * 8;
#pragma unroll
            for (int mt = 0; mt < 4; mt++) {
                uint32_t off = ((wm + mt * 16 + arow) * STRIDE + acol) * 2;
                ldmA(aH + mt * 4, sAh + off);
                ldmA(aL + mt * 4, sAl + off);
            }
            const int brow = lane & 7;
            const int bcol = kk + ((lane >> 3) & 1) * 8;
#pragma unroll
            for (int nt = 0; nt < 4; nt++) {
                uint32_t bh[2], bl[2];
                uint32_t off = ((wn + nt * 8 + brow) * STRIDE + bcol) * 2;
                ldmB(bh, sBh + off);
                ldmB(bl, sBl + off);
#pragma unroll
                for (int mt = 0; mt < 4; mt++) {
                    mma16816(acc[mt][nt], aH + mt * 4, bh);
                    mma16816(acc[mt][nt], aH + mt * 4, bl);
                    mma16816(acc[mt][nt], aL + mt * 4, bh);
                }
            }
        }
        __syncthreads();
    }

    // ---- epilogue ----
    float* dst;
    int ccol0;
    if (EPI == 0) {
        int part = n0 / DIM;
        dst   = (part == 0) ? O0 : (part == 1 ? O1 : O2);
        ccol0 = n0 - part * DIM;
    } else {
        dst   = O0;
        ccol0 = n0;
    }
#pragma unroll
    for (int mt = 0; mt < 4; mt++) {
#pragma unroll
        for (int nt = 0; nt < 4; nt++) {
            int row  = m0 + wm + mt * 16 + (lane >> 2);
            int bcol = n0 + wn + nt * 8 + (lane & 3) * 2;
            int col  = ccol0 + wn + nt * 8 + (lane & 3) * 2;
            float2 bb = *(const float2*)&bias[bcol];
            float2 v0, v1;
            v0.x = acc[mt][nt][0] + bb.x;  v0.y = acc[mt][nt][1] + bb.y;
            v1.x = acc[mt][nt][2] + bb.x;  v1.y = acc[mt][nt][3] + bb.y;
            *(float2*)&dst[(size_t)row * DIM + col]       = v0;
            *(float2*)&dst[(size_t)(row + 8) * DIM + col] = v1;
        }
    }
}

// ---------------------------------------------------------------------------
// RoPE (unchanged)
// ---------------------------------------------------------------------------
__global__ void rope_kernel(float* __restrict__ q, float* __restrict__ k,
                            const float* __restrict__ cosb,
                            const float* __restrict__ sinb)
{
    int t = blockIdx.x;
    for (int p = threadIdx.x; p < HEADS * 40; p += blockDim.x) {
        int h = p / 40, d = p - (p / 40) * 40;
        size_t base = (size_t)t * DIM + h * HD;
        float c0 = cosb[t * HD + d],      s0 = sinb[t * HD + d];
        float c1 = cosb[t * HD + d + 40], s1 = sinb[t * HD + d + 40];

        float a = q[base + d], b = q[base + d + 40];
        q[base + d]      = a * c0 - b * s0;
        q[base + d + 40] = b * c1 + a * s1;

        a = k[base + d]; b = k[base + d + 40];
        k[base + d]      = a * c0 - b * s0;
        k[base + d + 40] = b * c1 + a * s1;
    }
}

// ---------------------------------------------------------------------------
// Flash attention fp32 (unchanged this round)
// ---------------------------------------------------------------------------
__global__ __launch_bounds__(128)
void attn_kernel(const float* __restrict__ qb, const float* __restrict__ kb,
                 const float* __restrict__ vb, float* __restrict__ ob)
{
    __shared__ float Ks[64][84];
    __shared__ float Vs[64][84];

    const int chunk = blockIdx.z;
    const int head  = blockIdx.y;
    const int qt    = blockIdx.x;
    const int tid   = threadIdx.x;
    const int qrow  = chunk * CHUNK + qt * 128 + tid;

    const float scale = 0.11180339887498948f;

    float q[HD];
    const float* qp = qb + (size_t)qrow * DIM + head * HD;
#pragma unroll
    for (int d = 0; d < HD; d += 4) {
        float4 f = *(const float4*)&qp[d];
        q[d] = f.x * scale; q[d + 1] = f.y * scale;
        q[d + 2] = f.z * scale; q[d + 3] = f.w * scale;
    }

    float o[HD];
#pragma unroll
    for (int d = 0; d < HD; d++) o[d] = 0.f;
    float m = -1e30f, l = 0.f;

    for (int kt0 = 0; kt0 < CHUNK; kt0 += 64) {
        __syncthreads();
        const float* kp = kb + (size_t)(chunk * CHUNK + kt0) * DIM + head * HD;
        const float* vp = vb + (size_t)(chunk * CHUNK + kt0) * DIM + head * HD;
        for (int i = tid; i < 64 * 20; i += 128) {
            int r = i / 20;
            int c = (i - r * 20) * 4;
            *(float4*)&Ks[r][c] = *(const float4*)&kp[(size_t)r * DIM + c];
            *(float4*)&Vs[r][c] = *(const float4*)&vp[(size_t)r * DIM + c];
        }
        __syncthreads();

#pragma unroll 2
        for (int j = 0; j < 64; j++) {
            float s = 0.f;
#pragma unroll
            for (int d = 0; d < HD; d += 4) {
                float4 kk = *(float4*)&Ks[j][d];
                s += q[d] * kk.x + q[d + 1] * kk.y
                   + q[d + 2] * kk.z + q[d + 3] * kk.w;
            }
            if (s > m) {
                float alpha = __expf(m - s);
                m = s;
                l *= alpha;
#pragma unroll
                for (int d = 0; d < HD; d++) o[d] *= alpha;
            }
            float p = __expf(s - m);
            l += p;
#pragma unroll
            for (int d = 0; d < HD; d += 4) {
                float4 vv = *(float4*)&Vs[j][d];
                o[d]     += p * vv.x; o[d + 1] += p * vv.y;
                o[d + 2] += p * vv.z; o[d + 3] += p * vv.w;
            }
        }
    }

    float inv = 1.f / l;
    float* op = ob + (size_t)qrow * DIM + head * HD;
#pragma unroll
    for (int d = 0; d < HD; d += 4) {
        float4 f;
        f.x = o[d] * inv;     f.y = o[d + 1] * inv;
        f.z = o[d + 2] * inv; f.w = o[d + 3] * inv;
        *(float4*)&op[d] = f;
    }
}

// ---------------------------------------------------------------------------
// Launch
// ---------------------------------------------------------------------------
extern "C" void kernel_launch(void* const* d_in, const int* in_sizes, int n_in,
                              void* d_out, int out_size)
{
    const float* hs    = (const float*)d_in[0];
    const float* cosb  = (const float*)d_in[1];
    const float* sinb  = (const float*)d_in[2];
    const float* qkvw  = (const float*)d_in[3];
    const float* qkvb  = (const float*)d_in[4];
    const float* projw = (const float*)d_in[5];
    const float* projb = (const float*)d_in[6];
    float* out = (float*)d_out;
    (void)in_sizes; (void)n_in; (void)out_size;

    float *gq, *gk, *gv, *gao;
    cudaGetSymbolAddress((void**)&gq,  g_q);
    cudaGetSymbolAddress((void**)&gk,  g_k);
    cudaGetSymbolAddress((void**)&gv,  g_v);
    cudaGetSymbolAddress((void**)&gao, g_ao);

    __nv_bfloat16 *hsh, *hsl, *aoh, *aol, *wqh, *wql, *wph, *wpl;
    cudaGetSymbolAddress((void**)&hsh, g_hs_hi);
    cudaGetSymbolAddress((void**)&hsl, g_hs_lo);
    cudaGetSymbolAddress((void**)&aoh, g_ao_hi);
    cudaGetSymbolAddress((void**)&aol, g_ao_lo);
    cudaGetSymbolAddress((void**)&wqh, g_wq_hi);
    cudaGetSymbolAddress((void**)&wql, g_wq_lo);
    cudaGetSymbolAddress((void**)&wph, g_wp_hi);
    cudaGetSymbolAddress((void**)&wpl, g_wp_lo);

    const int SMEM = 2 * STAGE_B;  // 81920
    cudaFuncSetAttribute(mma_gemm<0>, cudaFuncAttributeMaxDynamicSharedMemorySize, SMEM);
    cudaFuncSetAttribute(mma_gemm<1>, cudaFuncAttributeMaxDynamicSharedMemorySize, SMEM);

    // split inputs + weights to bf16 hi/lo
    cvt_kernel<<<(TOTAL * K_DIM / 4 + 255) / 256, 256>>>(hs, hsh, hsl, TOTAL * K_DIM / 4);
    cvt_kernel<<<(N_QKV * K_DIM / 4 + 255) / 256, 256>>>(qkvw, wqh, wql, N_QKV * K_DIM / 4);
    cvt_kernel<<<(DIM * K_DIM / 4 + 255) / 256, 256>>>(projw, wph, wpl, DIM * K_DIM / 4);

    // QKV projection on tensor cores (HMMA)
    mma_gemm<0><<<dim3(N_QKV / 128, TOTAL / 128), 256, SMEM>>>(
        hsh, hsl, wqh, wql, qkvb, gq, gk, gv);

    rope_kernel<<<TOTAL, 640>>>(gq, gk, cosb, sinb);

    attn_kernel<<<dim3(CHUNK / 128, HEADS, NCHUNKS), 128>>>(gq, gk, gv, gao);

    // split attention output, then proj on tensor cores
    cvt_kernel<<<(TOTAL * K_DIM / 4 + 255) / 256, 256>>>(gao, aoh, aol, TOTAL * K_DIM / 4);
    mma_gemm<1><<<dim3(DIM / 128, TOTAL / 128), 256, SMEM>>>(
        aoh, aol, wph, wpl, projb, out, nullptr, nullptr);
}

// round 4
// speedup vs baseline: 3.3297x; 2.0036x over previous
#include <cuda_runtime.h>
#include <cuda_bf16.h>
#include <cstdint>
#include <cstddef>

#define TOTAL   8192
#define DIM     1280
#define HEADS   16
#define HD      80
#define NCHUNKS 8
#define CHUNK   1024
#define K_DIM   1280
#define N_QKV   3840

// ---------------- scratch (device globals) ----------------------------------
__device__ float g_q [TOTAL * DIM];
__device__ float g_k [TOTAL * DIM];
__device__ float g_v [TOTAL * DIM];

__device__ __nv_bfloat16 g_hs_hi[TOTAL * K_DIM];
__device__ __nv_bfloat16 g_hs_lo[TOTAL * K_DIM];
__device__ __nv_bfloat16 g_wq_hi[N_QKV * K_DIM];
__device__ __nv_bfloat16 g_wq_lo[N_QKV * K_DIM];
__device__ __nv_bfloat16 g_wp_hi[DIM * K_DIM];
__device__ __nv_bfloat16 g_wp_lo[DIM * K_DIM];

__device__ __nv_bfloat16 g_qh[TOTAL * DIM];
__device__ __nv_bfloat16 g_ql[TOTAL * DIM];
__device__ __nv_bfloat16 g_kh[TOTAL * DIM];
__device__ __nv_bfloat16 g_kl[TOTAL * DIM];
__device__ __nv_bfloat16 g_vh[TOTAL * DIM];
__device__ __nv_bfloat16 g_vl[TOTAL * DIM];
__device__ __nv_bfloat16 g_aoh[TOTAL * DIM];
__device__ __nv_bfloat16 g_aol[TOTAL * DIM];

// ---------------- PTX helpers ------------------------------------------------
__device__ __forceinline__ uint32_t smem_u32(const void* p) {
    uint32_t r;
    asm("{ .reg .u64 t; cvta.to.shared.u64 t, %1; cvt.u32.u64 %0, t; }"
        : "=r"(r) : "l"(p));
    return r;
}
__device__ __forceinline__ void cp16(uint32_t dst, const void* src) {
    asm volatile("cp.async.cg.shared.global [%0], [%1], 16;" :: "r"(dst), "l"(src));
}
__device__ __forceinline__ void ldmx4(uint32_t* a, uint32_t addr) {
    asm volatile("ldmatrix.sync.aligned.m8n8.x4.shared.b16 {%0,%1,%2,%3}, [%4];"
                 : "=r"(a[0]), "=r"(a[1]), "=r"(a[2]), "=r"(a[3]) : "r"(addr));
}
__device__ __forceinline__ void ldmx4t(uint32_t* a, uint32_t addr) {
    asm volatile("ldmatrix.sync.aligned.m8n8.x4.trans.shared.b16 {%0,%1,%2,%3}, [%4];"
                 : "=r"(a[0]), "=r"(a[1]), "=r"(a[2]), "=r"(a[3]) : "r"(addr));
}
__device__ __forceinline__ void ldmB(uint32_t* b, uint32_t addr) {
    asm volatile("ldmatrix.sync.aligned.m8n8.x2.shared.b16 {%0,%1}, [%2];"
                 : "=r"(b[0]), "=r"(b[1]) : "r"(addr));
}
__device__ __forceinline__ void mma16816(float* d, const uint32_t* a, const uint32_t* b) {
    asm volatile(
        "mma.sync.aligned.m16n8k16.row.col.f32.bf16.bf16.f32 "
        "{%0,%1,%2,%3}, {%4,%5,%6,%7}, {%8,%9}, {%0,%1,%2,%3};"
        : "+f"(d[0]), "+f"(d[1]), "+f"(d[2]), "+f"(d[3])
        : "r"(a[0]), "r"(a[1]), "r"(a[2]), "r"(a[3]), "r"(b[0]), "r"(b[1]));
}
__device__ __forceinline__ float ex2(float x) {
    float r;
    asm("ex2.approx.f32 %0, %1;" : "=f"(r) : "f"(x));
    return r;
}
__device__ __forceinline__ void split2(float a, float b, uint32_t& hi, uint32_t& lo) {
    __nv_bfloat162 h = __floats2bfloat162_rn(a, b);
    float ra = a - __bfloat162float(h.x);
    float rb = b - __bfloat162float(h.y);
    __nv_bfloat162 l = __floats2bfloat162_rn(ra, rb);
    hi = *(uint32_t*)&h;
    lo = *(uint32_t*)&l;
}

// ---------------------------------------------------------------------------
// fp32 -> bf16 hi/lo split
// ---------------------------------------------------------------------------
__global__ void cvt_kernel(const float* __restrict__ x,
                           __nv_bfloat16* __restrict__ hi,
                           __nv_bfloat16* __restrict__ lo, int n4)
{
    int i = blockIdx.x * blockDim.x + threadIdx.x;
    if (i >= n4) return;
    float4 f = ((const float4*)x)[i];
    uint32_t h0, l0, h1, l1;
    split2(f.x, f.y, h0, l0);
    split2(f.z, f.w, h1, l1);
    ((uint32_t*)hi)[i * 2 + 0] = h0; ((uint32_t*)hi)[i * 2 + 1] = h1;
    ((uint32_t*)lo)[i * 2 + 0] = l0; ((uint32_t*)lo)[i * 2 + 1] = l1;
}

// ---------------------------------------------------------------------------
// mma.sync GEMM (unchanged from R3)
// ---------------------------------------------------------------------------
#define KC      32
#define NCH     40
#define STRIDE  40
#define TILE_B  (128 * STRIDE * 2)
#define STAGE_B (4 * TILE_B)

template <int EPI>
__global__ __launch_bounds__(256, 2)
void mma_gemm(const __nv_bfloat16* __restrict__ Ah, const __nv_bfloat16* __restrict__ Al,
              const __nv_bfloat16* __restrict__ Bh, const __nv_bfloat16* __restrict__ Bl,
              const float* __restrict__ bias,
              float* __restrict__ O0, float* __restrict__ O1, float* __restrict__ O2)
{
    extern __shared__ __nv_bfloat16 smem[];
    const uint32_t sbase = smem_u32(smem);

    const int tid  = threadIdx.x;
    const int wid  = tid >> 5;
    const int lane = tid & 31;
    const int m0   = blockIdx.y * 128;
    const int n0   = blockIdx.x * 128;
    const int wm   = (wid >> 2) * 64;
    const int wn   = (wid & 3) * 32;

    const __nv_bfloat16* srcs[4] = {
        Ah + (size_t)m0 * K_DIM, Al + (size_t)m0 * K_DIM,
        Bh + (size_t)n0 * K_DIM, Bl + (size_t)n0 * K_DIM };

    auto load_chunk = [&](int stage, int ch) {
        const int k0 = ch * KC;
        const uint32_t sb = sbase + stage * STAGE_B;
#pragma unroll
        for (int t = 0; t < 8; t++) {
            int idx  = tid + t * 256;
            int tile = idx >> 9;
            int rem  = idx & 511;
            int row  = rem >> 2;
            int seg  = rem & 3;
            cp16(sb + tile * TILE_B + row * (STRIDE * 2) + seg * 16,
                 srcs[tile] + (size_t)row * K_DIM + k0 + seg * 8);
        }
        asm volatile("cp.async.commit_group;");
    };

    float acc[4][4][4];
#pragma unroll
    for (int i = 0; i < 4; i++)
#pragma unroll
        for (int j = 0; j < 4; j++)
#pragma unroll
            for (int r = 0; r < 4; r++) acc[i][j][r] = 0.f;

    load_chunk(0, 0);

    for (int ch = 0; ch < NCH; ch++) {
        const int s = ch & 1;
        if (ch + 1 < NCH) {
            load_chunk(1 - s, ch + 1);
            asm volatile("cp.async.wait_group 1;");
        } else {
            asm volatile("cp.async.wait_group 0;");
        }
        __syncthreads();

        const uint32_t sb  = sbase + s * STAGE_B;
        const uint32_t sAh = sb;
        const uint32_t sAl = sb + TILE_B;
        const uint32_t sBh = sb + 2 * TILE_B;
        const uint32_t sBl = sb + 3 * TILE_B;

#pragma unroll
        for (int kk = 0; kk < KC; kk += 16) {
            uint32_t aH[16], aL[16];
            const int arow = lane & 15;
            const int acol = kk + (lane >> 4) * 8;
#pragma unroll
            for (int mt = 0; mt < 4; mt++) {
                uint32_t off = ((wm + mt * 16 + arow) * STRIDE + acol) * 2;
                ldmx4(aH + mt * 4, sAh + off);
                ldmx4(aL + mt * 4, sAl + off);
            }
            const int brow = lane & 7;
            const int bcol = kk + ((lane >> 3) & 1) * 8;
#pragma unroll
            for (int nt = 0; nt < 4; nt++) {
                uint32_t bh[2], bl[2];
                uint32_t off = ((wn + nt * 8 + brow) * STRIDE + bcol) * 2;
                ldmB(bh, sBh + off);
                ldmB(bl, sBl + off);
#pragma unroll
                for (int mt = 0; mt < 4; mt++) {
                    mma16816(acc[mt][nt], aH + mt * 4, bh);
                    mma16816(acc[mt][nt], aH + mt * 4, bl);
                    mma16816(acc[mt][nt], aL + mt * 4, bh);
                }
            }
        }
        __syncthreads();
    }

    float* dst;
    int ccol0;
    if (EPI == 0) {
        int part = n0 / DIM;
        dst   = (part == 0) ? O0 : (part == 1 ? O1 : O2);
        ccol0 = n0 - part * DIM;
    } else {
        dst   = O0;
        ccol0 = n0;
    }
#pragma unroll
    for (int mt = 0; mt < 4; mt++) {
#pragma unroll
        for (int nt = 0; nt < 4; nt++) {
            int row  = m0 + wm + mt * 16 + (lane >> 2);
            int bcol = n0 + wn + nt * 8 + (lane & 3) * 2;
            int col  = ccol0 + wn + nt * 8 + (lane & 3) * 2;
            float2 bb = *(const float2*)&bias[bcol];
            float2 v0, v1;
            v0.x = acc[mt][nt][0] + bb.x;  v0.y = acc[mt][nt][1] + bb.y;
            v1.x = acc[mt][nt][2] + bb.x;  v1.y = acc[mt][nt][3] + bb.y;
            *(float2*)&dst[(size_t)row * DIM + col]       = v0;
            *(float2*)&dst[(size_t)(row + 8) * DIM + col] = v1;
        }
    }
}

// ---------------------------------------------------------------------------
// RoPE + scale + hi/lo split (q,k) and hi/lo split (v)
// One block per token, 640 threads.
// q is additionally scaled by HD^-0.5 * log2(e) (softmax done in base 2).
// ---------------------------------------------------------------------------
__global__ __launch_bounds__(640)
void rope_cvt(const float* __restrict__ gq, const float* __restrict__ gk,
              const float* __restrict__ gv,
              const float* __restrict__ cosb, const float* __restrict__ sinb,
              __nv_bfloat16* __restrict__ qh, __nv_bfloat16* __restrict__ ql,
              __nv_bfloat16* __restrict__ kh, __nv_bfloat16* __restrict__ kl,
              __nv_bfloat16* __restrict__ vh, __nv_bfloat16* __restrict__ vl)
{
    const float QSC = 0.11180339887498949f * 1.4426950408889634f;
    const int t = blockIdx.x;
    const int p = threadIdx.x;

    // q, k rope pairs
    {
        int h = p / 40, d = p - (p / 40) * 40;
        size_t base = (size_t)t * DIM + h * HD;
        float c0 = cosb[t * HD + d],      s0 = sinb[t * HD + d];
        float c1 = cosb[t * HD + d + 40], s1 = sinb[t * HD + d + 40];

        float a = gq[base + d], b = gq[base + d + 40];
        float q0 = (a * c0 - b * s0) * QSC;
        float q1 = (b * c1 + a * s1) * QSC;
        __nv_bfloat16 h0 = __float2bfloat16(q0);
        __nv_bfloat16 h1 = __float2bfloat16(q1);
        qh[base + d]      = h0;
        qh[base + d + 40] = h1;
        ql[base + d]      = __float2bfloat16(q0 - __bfloat162float(h0));
        ql[base + d + 40] = __float2bfloat16(q1 - __bfloat162float(h1));

        a = gk[base + d]; b = gk[base + d + 40];
        float k0 = a * c0 - b * s0;
        float k1 = b * c1 + a * s1;
        h0 = __float2bfloat16(k0);
        h1 = __float2bfloat16(k1);
        kh[base + d]      = h0;
        kh[base + d + 40] = h1;
        kl[base + d]      = __float2bfloat16(k0 - __bfloat162float(h0));
        kl[base + d + 40] = __float2bfloat16(k1 - __bfloat162float(h1));
    }
    // v split (2 consecutive elems per thread)
    {
        size_t i = (size_t)t * DIM + 2 * p;
        float2 f = *(const float2*)&gv[i];
        uint32_t hi, lo;
        split2(f.x, f.y, hi, lo);
        *(uint32_t*)&vh[i] = hi;
        *(uint32_t*)&vl[i] = lo;
    }
}

// ---------------------------------------------------------------------------
// Flash attention on mma.sync (bf16 hi/lo, fp32 softmax, base-2 exp).
// CTA: 128 q rows (8 warps x m16), 64-key K/V tiles, double buffered.
// Writes output directly as bf16 hi/lo for the proj GEMM.
// ---------------------------------------------------------------------------
#define AST     88                     // smem row stride (elems)
#define ATB     (64 * AST)             // elems per tile buffer (5632)
#define ASTAGE  (4 * ATB)              // elems per stage (Kh,Kl,Vh,Vl)

__global__ __launch_bounds__(256, 1)
void attn_mma(const __nv_bfloat16* __restrict__ qh, const __nv_bfloat16* __restrict__ ql,
              const __nv_bfloat16* __restrict__ kh, const __nv_bfloat16* __restrict__ kl,
              const __nv_bfloat16* __restrict__ vh, const __nv_bfloat16* __restrict__ vl,
              __nv_bfloat16* __restrict__ aoh, __nv_bfloat16* __restrict__ aol)
{
    extern __shared__ __nv_bfloat16 asmem[];
    const uint32_t sbase = smem_u32(asmem);

    const int tid   = threadIdx.x;
    const int wid   = tid >> 5;
    const int lane  = tid & 31;
    const int chunk = blockIdx.z;
    const int head  = blockIdx.y;
    const int q0    = blockIdx.x * 128;
    const int wm    = wid * 16;

    // ---- stage Q (hi/lo) through smem, ldmatrix into registers -------------
    {
        const __nv_bfloat16* srcq[2] = { qh, ql };
#pragma unroll
        for (int t = 0; t < 10; t++) {
            int idx = tid + t * 256;          // 0..2559
            int buf = idx / 1280;
            int rem = idx - buf * 1280;
            int row = rem / 10;
            int seg = rem - row * 10;
            cp16(sbase + (buf * (128 * AST) + row * AST + seg * 8) * 2,
                 srcq[buf] + (size_t)(chunk * CHUNK + q0 + row) * DIM + head * HD + seg * 8);
        }
        asm volatile("cp.async.commit_group;");
        asm volatile("cp.async.wait_group 0;");
    }
    __syncthreads();

    uint32_t aQh[5][4], aQl[5][4];
    {
        const int arow = lane & 15;
        const int acol8 = 8 * (lane >> 4);
#pragma unroll
        for (int ks = 0; ks < 5; ks++) {
            uint32_t off = ((wm + arow) * AST + ks * 16 + acol8) * 2;
            ldmx4(aQh[ks], sbase + off);
            ldmx4(aQl[ks], sbase + (128 * AST) * 2 + off);
        }
    }
    __syncthreads();   // everyone done with Q staging before KV overwrites

    // ---- KV tile loader -----------------------------------------------------
    const __nv_bfloat16* srckv[4] = { kh, kl, vh, vl };
    auto load_kv = [&](int stage, int t) {
        const int krow0 = chunk * CHUNK + t * 64;
        const uint32_t sb = sbase + (stage * ASTAGE) * 2;
#pragma unroll
        for (int it = 0; it < 10; it++) {
            int idx = tid + it * 256;         // 0..2559
            int buf = idx / 640;
            int rem = idx - buf * 640;
            int row = rem / 10;
            int seg = rem - row * 10;
            cp16(sb + (buf * ATB + row * AST + seg * 8) * 2,
                 srckv[buf] + (size_t)(krow0 + row) * DIM + head * HD + seg * 8);
        }
        asm volatile("cp.async.commit_group;");
    };

    float o[10][4];
#pragma unroll
    for (int i = 0; i < 10; i++)
#pragma unroll
        for (int r = 0; r < 4; r++) o[i][r] = 0.f;
    float mrow0 = -1e30f, mrow1 = -1e30f, lrow0 = 0.f, lrow1 = 0.f;

    load_kv(0, 0);

    for (int t = 0; t < 16; t++) {
        const int s = t & 1;
        if (t + 1 < 16) {
            load_kv(1 - s, t + 1);
            asm volatile("cp.async.wait_group 1;");
        } else {
            asm volatile("cp.async.wait_group 0;");
        }
        __syncthreads();

        const uint32_t sb  = sbase + (s * ASTAGE) * 2;
        const uint32_t sKh = sb;
        const uint32_t sKl = sb + ATB * 2;
        const uint32_t sVh = sb + 2 * ATB * 2;
        const uint32_t sVl = sb + 3 * ATB * 2;

        // ---- S = Q K^T (m16 x n64), 3 passes -------------------------------
        float S[8][4];
#pragma unroll
        for (int f = 0; f < 8; f++)
#pragma unroll
            for (int r = 0; r < 4; r++) S[f][r] = 0.f;

#pragma unroll
        for (int ks = 0; ks < 5; ks++) {
#pragma unroll
            for (int ng = 0; ng < 4; ng++) {
                uint32_t bh[4], bl[4];
                uint32_t off = ((ng * 16 + 8 * (lane >> 4) + (lane & 7)) * AST
                                + ks * 16 + 8 * ((lane >> 3) & 1)) * 2;
                ldmx4(bh, sKh + off);
                ldmx4(bl, sKl + off);
                mma16816(S[2 * ng],     aQh[ks], bh);
                mma16816(S[2 * ng],     aQl[ks], bh);
                mma16816(S[2 * ng],     aQh[ks], bl);
                mma16816(S[2 * ng + 1], aQh[ks], bh + 2);
                mma16816(S[2 * ng + 1], aQl[ks], bh + 2);
                mma16816(S[2 * ng + 1], aQh[ks], bl + 2);
            }
        }

        // ---- online softmax (base 2; scale folded into Q) ------------------
        float mx0 = S[0][0], mx1 = S[0][2];
#pragma unroll
        for (int f = 0; f < 8; f++) {
            mx0 = fmaxf(mx0, fmaxf(S[f][0], S[f][1]));
            mx1 = fmaxf(mx1, fmaxf(S[f][2], S[f][3]));
        }
        mx0 = fmaxf(mx0, __shfl_xor_sync(0xffffffff, mx0, 1));
        mx0 = fmaxf(mx0, __shfl_xor_sync(0xffffffff, mx0, 2));
        mx1 = fmaxf(mx1, __shfl_xor_sync(0xffffffff, mx1, 1));
        mx1 = fmaxf(mx1, __shfl_xor_sync(0xffffffff, mx1, 2));

        float mn0 = fmaxf(mrow0, mx0), mn1 = fmaxf(mrow1, mx1);
        float al0 = ex2(mrow0 - mn0),  al1 = ex2(mrow1 - mn1);
        mrow0 = mn0; mrow1 = mn1;
#pragma unroll
        for (int i = 0; i < 10; i++) {
            o[i][0] *= al0; o[i][1] *= al0;
            o[i][2] *= al1; o[i][3] *= al1;
        }
        float rs0 = 0.f, rs1 = 0.f;
#pragma unroll
        for (int f = 0; f < 8; f++) {
            S[f][0] = ex2(S[f][0] - mn0); rs0 += S[f][0];
            S[f][1] = ex2(S[f][1] - mn0); rs0 += S[f][1];
            S[f][2] = ex2(S[f][2] - mn1); rs1 += S[f][2];
            S[f][3] = ex2(S[f][3] - mn1); rs1 += S[f][3];
        }
        rs0 += __shfl_xor_sync(0xffffffff, rs0, 1);
        rs0 += __shfl_xor_sync(0xffffffff, rs0, 2);
        rs1 += __shfl_xor_sync(0xffffffff, rs1, 1);
        rs1 += __shfl_xor_sync(0xffffffff, rs1, 2);
        lrow0 = lrow0 * al0 + rs0;
        lrow1 = lrow1 * al1 + rs1;

        // ---- P (bf16 hi/lo a-frags) -----------------------------------------
        uint32_t pH[4][4], pL[4][4];
#pragma unroll
        for (int j = 0; j < 4; j++) {
            split2(S[2 * j][0],     S[2 * j][1],     pH[j][0], pL[j][0]);
            split2(S[2 * j][2],     S[2 * j][3],     pH[j][1], pL[j][1]);
            split2(S[2 * j + 1][0], S[2 * j + 1][1], pH[j][2], pL[j][2]);
            split2(S[2 * j + 1][2], S[2 * j + 1][3], pH[j][3], pL[j][3]);
        }

        // ---- O += P V (k64 x n80), 3 passes ---------------------------------
#pragma unroll
        for (int j = 0; j < 4; j++) {
#pragma unroll
            for (int ng = 0; ng < 5; ng++) {
                uint32_t bvh[4], bvl[4];
                uint32_t off = ((j * 16 + (lane & 15)) * AST
                                + ng * 16 + 8 * (lane >> 4)) * 2;
                ldmx4t(bvh, sVh + off);
                ldmx4t(bvl, sVl + off);
                mma16816(o[2 * ng],     pH[j], bvh);
                mma16816(o[2 * ng],     pL[j], bvh);
                mma16816(o[2 * ng],     pH[j], bvl);
                mma16816(o[2 * ng + 1], pH[j], bvh + 2);
                mma16816(o[2 * ng + 1], pL[j], bvh + 2);
                mma16816(o[2 * ng + 1], pH[j], bvl + 2);
            }
        }
        __syncthreads();
    }

    // ---- normalize + store bf16 hi/lo ---------------------------------------
    float inv0 = 1.f / lrow0, inv1 = 1.f / lrow1;
    const int row0 = chunk * CHUNK + q0 + wm + (lane >> 2);
    const int col0 = head * HD + 2 * (lane & 3);
#pragma unroll
    for (int nt = 0; nt < 10; nt++) {
        uint32_t hi, lo;
        size_t idx0 = (size_t)row0 * DIM + col0 + nt * 8;
        split2(o[nt][0] * inv0, o[nt][1] * inv0, hi, lo);
        *(uint32_t*)&aoh[idx0] = hi;
        *(uint32_t*)&aol[idx0] = lo;
        size_t idx1 = (size_t)(row0 + 8) * DIM + col0 + nt * 8;
        split2(o[nt][2] * inv1, o[nt][3] * inv1, hi, lo);
        *(uint32_t*)&aoh[idx1] = hi;
        *(uint32_t*)&aol[idx1] = lo;
    }
}

// ---------------------------------------------------------------------------
// Launch
// ---------------------------------------------------------------------------
extern "C" void kernel_launch(void* const* d_in, const int* in_sizes, int n_in,
                              void* d_out, int out_size)
{
    const float* hs    = (const float*)d_in[0];
    const float* cosb  = (const float*)d_in[1];
    const float* sinb  = (const float*)d_in[2];
    const float* qkvw  = (const float*)d_in[3];
    const float* qkvb  = (const float*)d_in[4];
    const float* projw = (const float*)d_in[5];
    const float* projb = (const float*)d_in[6];
    float* out = (float*)d_out;
    (void)in_sizes; (void)n_in; (void)out_size;

    float *gq, *gk, *gv;
    cudaGetSymbolAddress((void**)&gq, g_q);
    cudaGetSymbolAddress((void**)&gk, g_k);
    cudaGetSymbolAddress((void**)&gv, g_v);

    __nv_bfloat16 *hsh, *hsl, *wqh, *wql, *wph, *wpl;
    __nv_bfloat16 *qh, *ql, *kh, *kl, *vh, *vl, *aoh, *aol;
    cudaGetSymbolAddress((void**)&hsh, g_hs_hi);
    cudaGetSymbolAddress((void**)&hsl, g_hs_lo);
    cudaGetSymbolAddress((void**)&wqh, g_wq_hi);
    cudaGetSymbolAddress((void**)&wql, g_wq_lo);
    cudaGetSymbolAddress((void**)&wph, g_wp_hi);
    cudaGetSymbolAddress((void**)&wpl, g_wp_lo);
    cudaGetSymbolAddress((void**)&qh, g_qh);
    cudaGetSymbolAddress((void**)&ql, g_ql);
    cudaGetSymbolAddress((void**)&kh, g_kh);
    cudaGetSymbolAddress((void**)&kl, g_kl);
    cudaGetSymbolAddress((void**)&vh, g_vh);
    cudaGetSymbolAddress((void**)&vl, g_vl);
    cudaGetSymbolAddress((void**)&aoh, g_aoh);
    cudaGetSymbolAddress((void**)&aol, g_aol);

    const int SMEM  = 2 * STAGE_B;                 // 81920
    const int ASMEM = 2 * ASTAGE * 2;              // 90112
    cudaFuncSetAttribute(mma_gemm<0>, cudaFuncAttributeMaxDynamicSharedMemorySize, SMEM);
    cudaFuncSetAttribute(mma_gemm<1>, cudaFuncAttributeMaxDynamicSharedMemorySize, SMEM);
    cudaFuncSetAttribute(attn_mma,    cudaFuncAttributeMaxDynamicSharedMemorySize, ASMEM);

    cvt_kernel<<<(TOTAL * K_DIM / 4 + 255) / 256, 256>>>(hs, hsh, hsl, TOTAL * K_DIM / 4);
    cvt_kernel<<<(N_QKV * K_DIM / 4 + 255) / 256, 256>>>(qkvw, wqh, wql, N_QKV * K_DIM / 4);
    cvt_kernel<<<(DIM * K_DIM / 4 + 255) / 256, 256>>>(projw, wph, wpl, DIM * K_DIM / 4);

    mma_gemm<0><<<dim3(N_QKV / 128, TOTAL / 128), 256, SMEM>>>(
        hsh, hsl, wqh, wql, qkvb, gq, gk, gv);

    rope_cvt<<<TOTAL, 640>>>(gq, gk, gv, cosb, sinb, qh, ql, kh, kl, vh, vl);

    attn_mma<<<dim3(CHUNK / 128, HEADS, NCHUNKS), 256, ASMEM>>>(
        qh, ql, kh, kl, vh, vl, aoh, aol);

    mma_gemm<1><<<dim3(DIM / 128, TOTAL / 128), 256, SMEM>>>(
        aoh, aol, wph, wpl, projb, out, nullptr, nullptr);
}